// round 3
// baseline (speedup 1.0000x reference)
#include <cuda_runtime.h>
#include <math.h>

#define Bsz 128
#define Tt  512
#define H3  1536
#define BT  65536
#define NCTA 128

typedef unsigned long long ull;

__device__ float g_G[201326592];   // [dir][b*T+t][1536]
__device__ float g_out[67108864];  // [b][t][1024]
__device__ float g_h[262144];      // [phase][dir][b][512]
__device__ float g_scores[65536];
__device__ int   g_tok2[131072];
__device__ unsigned g_cnt, g_gen, g_done;

// packed f32x2 helpers (FFMA2 — only reachable via PTX)
__device__ __forceinline__ ull ffma2(ull a, ull b, ull c)
{
    ull d;
    asm("fma.rn.f32x2 %0, %1, %2, %3;" : "=l"(d) : "l"(a), "l"(b), "l"(c));
    return d;
}
__device__ __forceinline__ float2 unpack2(ull v)
{
    float2 r;
    asm("mov.b64 {%0,%1}, %2;" : "=f"(r.x), "=f"(r.y) : "l"(v));
    return r;
}

// ---------------------------------------------------------------- K0
__global__ void k_init(const int* __restrict__ tokens, const int* __restrict__ lengths)
{
    int i = blockIdx.x * blockDim.x + threadIdx.x;
    if (i >= BT) return;
    int b = i >> 9, t = i & 511;
    g_tok2[i] = tokens[i];
    int rt = lengths[b] - 1 - t;
    if (rt < 0) rt = 0;
    g_tok2[BT + i] = tokens[(b << 9) + rt];
    g_scores[i] = 0.f;
}

// ---------------------------------------------------------------- K1: G = emb[tok] @ Wih^T + bih  (f32x2)
__global__ void __launch_bounds__(512) k_gemm_ih(
    const float* __restrict__ emb,
    const float* __restrict__ Wf, const float* __restrict__ bf,
    const float* __restrict__ Wb, const float* __restrict__ bb)
{
    const int d = blockIdx.z;
    const float* W    = d ? Wb : Wf;
    const float* bias = d ? bb : bf;
    __shared__ __align__(16) float2 As2[4][128];
    __shared__ __align__(16) float2 Bs2[4][128];
    __shared__ int toks[128];
    int tid = threadIdx.x;
    int mb = blockIdx.y * 128, nb = blockIdx.x * 128;   // nb fastest: A-row L2 reuse
    if (tid < 128) toks[tid] = g_tok2[d * BT + mb + tid];
    __syncthreads();
    int lm = tid >> 2, kkl = tid & 3;
    const float* Ap = emb + (long)toks[lm] * 512 + kkl * 2;
    const float* Bp = W   + (long)(nb + lm) * 512 + kkl * 2;
    int tx = tid & 31, ty = tid >> 5;
    int n0 = tx * 4, m0 = ty * 8;

    ull acc[8][4];
    #pragma unroll
    for (int i = 0; i < 8; i++)
        #pragma unroll
        for (int j = 0; j < 4; j++) acc[i][j] = 0ull;

    float2 pa = *(const float2*)Ap;
    float2 pb = *(const float2*)Bp;

    for (int kt = 0; kt < 512; kt += 8) {
        As2[kkl][lm] = pa;
        Bs2[kkl][lm] = pb;
        __syncthreads();
        if (kt + 8 < 512) {
            pa = *(const float2*)(Ap + kt + 8);
            pb = *(const float2*)(Bp + kt + 8);
        }
        #pragma unroll
        for (int kk = 0; kk < 4; kk++) {
            ull av[8], bv[4];
            #pragma unroll
            for (int q = 0; q < 4; q++) {
                ulonglong2 v = *(const ulonglong2*)&As2[kk][m0 + q * 2];
                av[q * 2] = v.x; av[q * 2 + 1] = v.y;
            }
            {
                ulonglong2 v0 = *(const ulonglong2*)&Bs2[kk][n0];
                ulonglong2 v1 = *(const ulonglong2*)&Bs2[kk][n0 + 2];
                bv[0] = v0.x; bv[1] = v0.y; bv[2] = v1.x; bv[3] = v1.y;
            }
            #pragma unroll
            for (int i = 0; i < 8; i++)
                #pragma unroll
                for (int j = 0; j < 4; j++)
                    acc[i][j] = ffma2(av[i], bv[j], acc[i][j]);
        }
        __syncthreads();
    }
    float* Cb = g_G + (long)d * BT * H3;
    #pragma unroll
    for (int i = 0; i < 8; i++) {
        float4 o;
        float2 p0 = unpack2(acc[i][0]);
        float2 p1 = unpack2(acc[i][1]);
        float2 p2 = unpack2(acc[i][2]);
        float2 p3 = unpack2(acc[i][3]);
        o.x = p0.x + p0.y + bias[nb + n0 + 0];
        o.y = p1.x + p1.y + bias[nb + n0 + 1];
        o.z = p2.x + p2.y + bias[nb + n0 + 2];
        o.w = p3.x + p3.y + bias[nb + n0 + 3];
        *(float4*)(Cb + (long)(mb + m0 + i) * H3 + nb + n0) = o;
    }
}

// ---------------------------------------------------------------- grid barrier (monotonic)
__device__ __forceinline__ void grid_barrier(unsigned target)
{
    __syncthreads();
    if (threadIdx.x == 0) {
        __threadfence();
        unsigned a = atomicAdd(&g_cnt, 1u) + 1u;
        if (a == target * NCTA) {
            atomicAdd(&g_gen, 1u);
        } else {
            while (*(volatile unsigned*)&g_gen < target) { }
        }
        __threadfence();
    }
    __syncthreads();
}

// ---------------------------------------------------------------- K2: persistent bi-GRU recurrence (f32x2)
extern __shared__ float smem_gru[];
__global__ void __launch_bounds__(256) k_gru(
    const float* __restrict__ Whh_f, const float* __restrict__ bhh_f,
    const float* __restrict__ Whh_b, const float* __restrict__ bhh_b,
    const int*   __restrict__ lengths)
{
    ull*   Ws2 = (ull*)smem_gru;          // [256 kpairs][96 rows]
    float* hsm = smem_gru + 512 * 96;     // [32 b][72]
    int tid = threadIdx.x;
    int cid = blockIdx.x;
    int d  = cid >> 6;
    int r  = cid & 63;
    int kg = r & 15;       // unit group (32 hidden units)
    int bg = r >> 4;       // batch group (32 rows)
    const float* Whh = d ? Whh_b : Whh_f;
    const float* bhh = d ? bhh_b : bhh_f;
    int tx = tid & 31, ty = tid >> 5;
    int u  = kg * 32 + tx;
    int b0 = bg * 32 + ty * 4;

    // cache the CTA's 96 Whh rows, k-pair transposed: Ws2[kp][row] = (W[row][2kp], W[row][2kp+1])
    for (int idx = tid; idx < 96 * 128; idx += 256) {
        int row = idx >> 7;                 // local j = g*32 + jl
        int g = row >> 5, jl = row & 31;
        int k4 = (idx & 127) << 2;
        float4 w = *(const float4*)(Whh + (long)(g * 512 + kg * 32 + jl) * 512 + k4);
        float2* wd = (float2*)Ws2;
        wd[((k4 >> 1) + 0) * 96 + row] = make_float2(w.x, w.y);
        wd[((k4 >> 1) + 1) * 96 + row] = make_float2(w.z, w.w);
    }
    float bh0 = bhh[u], bh1 = bhh[512 + u], bh2 = bhh[1024 + u];
    int len[4];
    #pragma unroll
    for (int i = 0; i < 4; i++) len[i] = lengths[b0 + i];

    for (int i = tid; i < 1024; i += 256) {
        int bb = bg * 32 + (i >> 5);
        int uu = kg * 32 + (i & 31);
        g_h[((0 * 2 + d) * 128 + bb) * 512 + uu] = 0.f;
    }
    grid_barrier(1);

    for (int t = 0; t < 512; ++t) {
        int p = t & 1;
        const float* hbase = g_h + (p * 2 + d) * 128 * 512;
        float ir[4], iz[4], inn[4];
        #pragma unroll
        for (int i = 0; i < 4; i++) {
            const float* gp = g_G + (long)d * BT * H3 + ((long)(b0 + i) * 512 + t) * H3;
            ir[i]  = __ldg(gp + u);
            iz[i]  = __ldg(gp + 512 + u);
            inn[i] = __ldg(gp + 1024 + u);
        }
        ull a0[4] = {0,0,0,0}, a1[4] = {0,0,0,0}, a2[4] = {0,0,0,0};

        for (int kc = 0; kc < 512; kc += 64) {
            __syncthreads();
            {   // stage h chunk: 32 b x 64 k via L2
                int bl = tid >> 3;
                int kk = (tid & 7) << 3;
                const float* hp = hbase + (bg * 32 + bl) * 512 + kc + kk;
                float4 h0 = __ldcg((const float4*)hp);
                float4 h1 = __ldcg((const float4*)(hp + 4));
                float* dst = hsm + bl * 72 + kk;
                *(float4*)dst       = h0;
                *(float4*)(dst + 4) = h1;
            }
            __syncthreads();
            #pragma unroll 8
            for (int kk = 0; kk < 32; kk++) {       // 32 k-pairs
                const ull* wp = Ws2 + ((kc >> 1) + kk) * 96;
                ull w0 = wp[tx], w1 = wp[32 + tx], w2 = wp[64 + tx];
                #pragma unroll
                for (int i = 0; i < 4; i++) {
                    ull hv = *(const ull*)&hsm[(ty * 4 + i) * 72 + kk * 2];
                    a0[i] = ffma2(hv, w0, a0[i]);
                    a1[i] = ffma2(hv, w1, a1[i]);
                    a2[i] = ffma2(hv, w2, a2[i]);
                }
            }
        }
        float* hw = g_h + ((p ^ 1) * 2 + d) * 128 * 512;
        #pragma unroll
        for (int i = 0; i < 4; i++) {
            int bb = b0 + i;
            float hprev = __ldcg(hbase + bb * 512 + u);
            float2 s0 = unpack2(a0[i]);
            float2 s1 = unpack2(a1[i]);
            float2 s2 = unpack2(a2[i]);
            float rr = 1.f / (1.f + expf(-(ir[i]  + s0.x + s0.y + bh0)));
            float zz = 1.f / (1.f + expf(-(iz[i]  + s1.x + s1.y + bh1)));
            float nn = tanhf(inn[i] + rr * (s2.x + s2.y + bh2));
            float hn = (1.f - zz) * nn + zz * hprev;
            bool m = (t < len[i]);
            hw[bb * 512 + u] = m ? hn : hprev;
            float* ob = g_out + (long)bb * 512 * 1024;
            if (d == 0) {
                ob[(long)t * 1024 + u] = m ? hn : 0.f;
            } else {
                int row = m ? (len[i] - 1 - t) : t;
                ob[(long)row * 1024 + 512 + u] = m ? hn : 0.f;
            }
        }
        grid_barrier((unsigned)(t + 2));
    }
    __syncthreads();
    if (tid == 0) {
        unsigned old = atomicAdd(&g_done, 1u);
        if (old == NCTA - 1) { g_cnt = 0; g_gen = 0; g_done = 0; __threadfence(); }
    }
}

// ---------------------------------------------------------------- K3: scores += tanh(out@Wp^T+bp) . ctx  (f32x2)
__global__ void __launch_bounds__(512) k_gemm_proj(
    const float* __restrict__ Wp, const float* __restrict__ bp,
    const float* __restrict__ ctx)
{
    __shared__ __align__(16) float2 As2[4][128];
    __shared__ __align__(16) float2 Bs2[4][128];
    int tid = threadIdx.x;
    int mb = blockIdx.y * 128, nb = blockIdx.x * 128;
    int lm = tid >> 2, kkl = tid & 3;
    const float* Ap = (const float*)g_out + (long)(mb + lm) * 1024 + kkl * 2;
    const float* Bp = Wp + (long)(nb + lm) * 1024 + kkl * 2;
    int tx = tid & 31, ty = tid >> 5;
    int n0 = tx * 4, m0 = ty * 8;

    ull acc[8][4];
    #pragma unroll
    for (int i = 0; i < 8; i++)
        #pragma unroll
        for (int j = 0; j < 4; j++) acc[i][j] = 0ull;

    float2 pa = *(const float2*)Ap;
    float2 pb = *(const float2*)Bp;

    for (int kt = 0; kt < 1024; kt += 8) {
        As2[kkl][lm] = pa;
        Bs2[kkl][lm] = pb;
        __syncthreads();
        if (kt + 8 < 1024) {
            pa = *(const float2*)(Ap + kt + 8);
            pb = *(const float2*)(Bp + kt + 8);
        }
        #pragma unroll
        for (int kk = 0; kk < 4; kk++) {
            ull av[8], bv[4];
            #pragma unroll
            for (int q = 0; q < 4; q++) {
                ulonglong2 v = *(const ulonglong2*)&As2[kk][m0 + q * 2];
                av[q * 2] = v.x; av[q * 2 + 1] = v.y;
            }
            {
                ulonglong2 v0 = *(const ulonglong2*)&Bs2[kk][n0];
                ulonglong2 v1 = *(const ulonglong2*)&Bs2[kk][n0 + 2];
                bv[0] = v0.x; bv[1] = v0.y; bv[2] = v1.x; bv[3] = v1.y;
            }
            #pragma unroll
            for (int i = 0; i < 8; i++)
                #pragma unroll
                for (int j = 0; j < 4; j++)
                    acc[i][j] = ffma2(av[i], bv[j], acc[i][j]);
        }
        __syncthreads();
    }
    #pragma unroll
    for (int i = 0; i < 8; i++) {
        float part = 0.f;
        #pragma unroll
        for (int j = 0; j < 4; j++) {
            float2 p = unpack2(acc[i][j]);
            float v = tanhf(p.x + p.y + bp[nb + n0 + j]);
            part = fmaf(v, ctx[nb + n0 + j], part);
        }
        #pragma unroll
        for (int o = 16; o > 0; o >>= 1)
            part += __shfl_xor_sync(0xffffffffu, part, o);
        if (tx == 0) atomicAdd(&g_scores[mb + m0 + i], part);
    }
}

// ---------------------------------------------------------------- K4: softmax + pooling + SELU + logits
__global__ void __launch_bounds__(512) k_final(
    const int* __restrict__ lengths,
    const float* __restrict__ Wl, const float* __restrict__ bl,
    float* __restrict__ out, int out_size)
{
    __shared__ float sh[512];
    __shared__ float attn[512];
    __shared__ float lg[2];
    int b = blockIdx.x, tid = threadIdx.x;
    int len = lengths[b];
    float s = (tid < len) ? g_scores[b * 512 + tid] : -1e30f;
    sh[tid] = s; __syncthreads();
    for (int o = 256; o > 0; o >>= 1) { if (tid < o) sh[tid] = fmaxf(sh[tid], sh[tid + o]); __syncthreads(); }
    float mx = sh[0]; __syncthreads();
    float e = (tid < len) ? expf(s - mx) : 0.f;
    sh[tid] = e; __syncthreads();
    for (int o = 256; o > 0; o >>= 1) { if (tid < o) sh[tid] += sh[tid + o]; __syncthreads(); }
    float a = e / sh[0];
    attn[tid] = a;
    int attn_ofs = (out_size >= 65792) ? 256 : 0;
    if (out_size != 256) out[attn_ofs + b * 512 + tid] = a;
    if (tid == 0) { lg[0] = 0.f; lg[1] = 0.f; }
    __syncthreads();

    const float* ob = g_out + (long)b * 512 * 1024;
    float s0 = 0.f, s1 = 0.f;
    for (int t = 0; t < 512; t++) {
        float at = attn[t];
        s0 = fmaf(at, ob[(long)t * 1024 + tid],       s0);
        s1 = fmaf(at, ob[(long)t * 1024 + 512 + tid], s1);
    }
    const float SC = 1.0507009873554805f, AL = 1.6732632423543772f;
    s0 = (s0 > 0.f) ? SC * s0 : SC * AL * (expf(s0) - 1.f);
    s1 = (s1 > 0.f) ? SC * s1 : SC * AL * (expf(s1) - 1.f);
    float p0 = s0 * Wl[tid]        + s1 * Wl[512 + tid];
    float p1 = s0 * Wl[1024 + tid] + s1 * Wl[1536 + tid];
    #pragma unroll
    for (int o = 16; o > 0; o >>= 1) {
        p0 += __shfl_xor_sync(0xffffffffu, p0, o);
        p1 += __shfl_xor_sync(0xffffffffu, p1, o);
    }
    if ((tid & 31) == 0) { atomicAdd(&lg[0], p0); atomicAdd(&lg[1], p1); }
    __syncthreads();
    if (tid < 2 && out_size != 65536) out[b * 2 + tid] = lg[tid] + bl[tid];
}

// ---------------------------------------------------------------- launch
extern "C" void kernel_launch(void* const* d_in, const int* in_sizes, int n_in,
                              void* d_out, int out_size)
{
    const int*   tokens  = (const int*)d_in[0];
    const int*   lengths = (const int*)d_in[1];
    const float* emb     = (const float*)d_in[2];
    const float* Wih_f   = (const float*)d_in[3];
    const float* Whh_f   = (const float*)d_in[4];
    const float* bih_f   = (const float*)d_in[5];
    const float* bhh_f   = (const float*)d_in[6];
    const float* Wih_b   = (const float*)d_in[7];
    const float* Whh_b   = (const float*)d_in[8];
    const float* bih_b   = (const float*)d_in[9];
    const float* bhh_b   = (const float*)d_in[10];
    const float* Wp      = (const float*)d_in[11];
    const float* bp      = (const float*)d_in[12];
    const float* ctx     = (const float*)d_in[13];
    const float* Wl      = (const float*)d_in[14];
    const float* bl      = (const float*)d_in[15];
    float* out = (float*)d_out;

    k_init<<<BT / 256, 256>>>(tokens, lengths);

    dim3 g1(12, 512, 2);
    k_gemm_ih<<<g1, 512>>>(emb, Wih_f, bih_f, Wih_b, bih_b);

    int smem_bytes = (512 * 96 + 32 * 72) * 4;
    cudaFuncSetAttribute(k_gru, cudaFuncAttributeMaxDynamicSharedMemorySize, smem_bytes);
    k_gru<<<NCTA, 256, smem_bytes>>>(Whh_f, bhh_f, Whh_b, bhh_b, lengths);

    dim3 g3(4, 512);
    k_gemm_proj<<<g3, 512>>>(Wp, bp, ctx);

    k_final<<<Bsz, 512>>>(lengths, Wl, bl, out, out_size);
}

// round 5
// speedup vs baseline: 1.4036x; 1.4036x over previous
#include <cuda_runtime.h>
#include <cuda_bf16.h>
#include <math.h>
#include <stdint.h>

#define Bsz 128
#define Tt  512
#define H3  1536
#define BT  65536
#define NCTA 128

__device__ float g_G[201326592];   // [dir][b*T+t][1536]
__device__ float g_out[67108864];  // [b][t][1024]
__device__ float g_h[262144];      // [phase][dir][b][512]
__device__ float g_scores[65536];
__device__ int   g_tok2[131072];
__device__ unsigned g_cnt, g_gen, g_done;

// bf16 split operands
__device__ __nv_bfloat16 g_Xh[67108864];  // [2*BT][512]
__device__ __nv_bfloat16 g_Xl[67108864];
__device__ __nv_bfloat16 g_Wh[1572864];   // [2][1536][512]
__device__ __nv_bfloat16 g_Wl[1572864];

// ---------------------------------------------------------------- helpers
__device__ __forceinline__ uint32_t smem_u32(const void* p)
{
    uint32_t a;
    asm("{ .reg .u64 t; cvta.to.shared.u64 t, %1; cvt.u32.u64 %0, t; }" : "=r"(a) : "l"(p));
    return a;
}
__device__ __forceinline__ void cp16(uint32_t dst, const void* src)
{
    asm volatile("cp.async.cg.shared.global [%0], [%1], 16;" :: "r"(dst), "l"(src) : "memory");
}
__device__ __forceinline__ void cp_commit()
{
    asm volatile("cp.async.commit_group;" ::: "memory");
}
__device__ __forceinline__ void ldsm4(uint32_t* r, uint32_t addr)
{
    asm volatile("ldmatrix.sync.aligned.m8n8.x4.shared.b16 {%0,%1,%2,%3}, [%4];"
                 : "=r"(r[0]), "=r"(r[1]), "=r"(r[2]), "=r"(r[3]) : "r"(addr));
}
__device__ __forceinline__ void mma16816(float* c, const uint32_t* a, uint32_t b0, uint32_t b1)
{
    asm volatile("mma.sync.aligned.m16n8k16.row.col.f32.bf16.bf16.f32 "
                 "{%0,%1,%2,%3}, {%4,%5,%6,%7}, {%8,%9}, {%0,%1,%2,%3};"
                 : "+f"(c[0]), "+f"(c[1]), "+f"(c[2]), "+f"(c[3])
                 : "r"(a[0]), "r"(a[1]), "r"(a[2]), "r"(a[3]), "r"(b0), "r"(b1));
}

// ---------------------------------------------------------------- K0
__global__ void k_init(const int* __restrict__ tokens, const int* __restrict__ lengths)
{
    int i = blockIdx.x * blockDim.x + threadIdx.x;
    if (i >= BT) return;
    int b = i >> 9, t = i & 511;
    g_tok2[i] = tokens[i];
    int rt = lengths[b] - 1 - t;
    if (rt < 0) rt = 0;
    g_tok2[BT + i] = tokens[(b << 9) + rt];
    g_scores[i] = 0.f;
}

// ---------------------------------------------------------------- conv: X = emb[tok2] split hi/lo
__global__ void k_convX(const float* __restrict__ emb)
{
    size_t idx = (size_t)blockIdx.x * 256 + threadIdx.x;
    size_t e = idx * 4;
    size_t row = e >> 9;
    int k = (int)(e & 511);
    int tok = g_tok2[row];
    float4 v = *(const float4*)(emb + (size_t)tok * 512 + k);
    float vv[4] = {v.x, v.y, v.z, v.w};
    __nv_bfloat16 h[4], l[4];
    #pragma unroll
    for (int j = 0; j < 4; j++) {
        h[j] = __float2bfloat16(vv[j]);
        l[j] = __float2bfloat16(vv[j] - __bfloat162float(h[j]));
    }
    __nv_bfloat162* ph = (__nv_bfloat162*)(g_Xh + row * 512 + k);
    __nv_bfloat162* pl = (__nv_bfloat162*)(g_Xl + row * 512 + k);
    ph[0] = __nv_bfloat162{h[0], h[1]}; ph[1] = __nv_bfloat162{h[2], h[3]};
    pl[0] = __nv_bfloat162{l[0], l[1]}; pl[1] = __nv_bfloat162{l[2], l[3]};
}

__global__ void k_convW(const float* __restrict__ Wf, const float* __restrict__ Wb)
{
    size_t idx = (size_t)blockIdx.x * 256 + threadIdx.x;
    size_t e = idx * 4;
    size_t row = e >> 9;                // 0..3071
    int k = (int)(e & 511);
    int d = (int)(row >= 1536);
    size_t n = row - (size_t)d * 1536;
    const float* W = d ? Wb : Wf;
    float4 v = *(const float4*)(W + n * 512 + k);
    float vv[4] = {v.x, v.y, v.z, v.w};
    __nv_bfloat16 h[4], l[4];
    #pragma unroll
    for (int j = 0; j < 4; j++) {
        h[j] = __float2bfloat16(vv[j]);
        l[j] = __float2bfloat16(vv[j] - __bfloat162float(h[j]));
    }
    __nv_bfloat162* ph = (__nv_bfloat162*)(g_Wh + row * 512 + k);
    __nv_bfloat162* pl = (__nv_bfloat162*)(g_Wl + row * 512 + k);
    ph[0] = __nv_bfloat162{h[0], h[1]}; ph[1] = __nv_bfloat162{h[2], h[3]};
    pl[0] = __nv_bfloat162{l[0], l[1]}; pl[1] = __nv_bfloat162{l[2], l[3]};
}

// ---------------------------------------------------------------- K1: mma.sync split-bf16 GEMM
// CTA 128x128, K chunks of 32, double-buffered cp.async smem.
// Per buffer (40960 B): Ah@0, Al@10240, Bh@20480, Bl@30720; rows stride 80 B.
#define TBUF 40960
#define SMEM_TC (2 * TBUF)
extern __shared__ char sm_tc[];

__device__ __forceinline__ void issue_chunk(
    uint32_t sbase, const __nv_bfloat16* Xh, const __nv_bfloat16* Xl,
    const __nv_bfloat16* Wh, const __nv_bfloat16* Wl, int k0, int tid)
{
    const __nv_bfloat16* srcs[4] = {Xh, Xl, Wh, Wl};
    #pragma unroll
    for (int j = 0; j < 8; j++) {
        int L = tid + j * 256;
        int mat = L >> 9, rem = L & 511, row = rem >> 2, q = rem & 3;
        const char* gp = (const char*)(srcs[mat] + (size_t)row * 512 + k0) + q * 16;
        cp16(sbase + mat * 10240 + row * 80 + q * 16, gp);
    }
    cp_commit();
}

__global__ void __launch_bounds__(256) k_gemm_ih_tc(
    const float* __restrict__ bf, const float* __restrict__ bb)
{
    uint32_t sb = smem_u32(sm_tc);
    int tid = threadIdx.x, wid = tid >> 5, lane = tid & 31;
    int d = blockIdx.z, mb = blockIdx.y * 128, nb = blockIdx.x * 128;
    const float* bias = (d ? bb : bf) + nb;

    const __nv_bfloat16* Xh = g_Xh + (size_t)(d * BT + mb) * 512;
    const __nv_bfloat16* Xl = g_Xl + (size_t)(d * BT + mb) * 512;
    const __nv_bfloat16* Wh = g_Wh + (size_t)(d * 1536 + nb) * 512;
    const __nv_bfloat16* Wl = g_Wl + (size_t)(d * 1536 + nb) * 512;

    int wm = (wid & 1) * 64;      // warp m offset
    int wn = (wid >> 1) * 32;     // warp n offset

    float acc[4][4][4];
    #pragma unroll
    for (int f = 0; f < 4; f++)
        #pragma unroll
        for (int n = 0; n < 4; n++)
            #pragma unroll
            for (int r = 0; r < 4; r++) acc[f][n][r] = 0.f;

    issue_chunk(sb,        Xh, Xl, Wh, Wl, 0,  tid);
    issue_chunk(sb + TBUF, Xh, Xl, Wh, Wl, 32, tid);

    // lane addressing pieces (byte offsets into a 128x(40) bf16 tile, stride 80B)
    int arow = (lane & 15);
    int ahk  = ((lane >> 4) & 1) * 16;
    int brow = (lane & 7) + ((lane >> 4) & 1) * 8;
    int bhk  = ((lane >> 3) & 1) * 16;

    for (int c = 0; c < 16; c++) {
        if (c == 15) asm volatile("cp.async.wait_group 0;" ::: "memory");
        else         asm volatile("cp.async.wait_group 1;" ::: "memory");
        __syncthreads();
        uint32_t base = sb + (c & 1) * TBUF;
        uint32_t aA = base +         (wm + arow) * 80 + ahk;
        uint32_t aB = base + 20480 + (wn + brow) * 80 + bhk;

        #pragma unroll
        for (int s = 0; s < 2; s++) {
            uint32_t ah[4][4], al[4][4], bh[2][4], bl[2][4];
            #pragma unroll
            for (int f = 0; f < 4; f++) {
                ldsm4(ah[f], aA + f * 16 * 80 + s * 32);
                ldsm4(al[f], aA + 10240 + f * 16 * 80 + s * 32);
            }
            #pragma unroll
            for (int g = 0; g < 2; g++) {
                ldsm4(bh[g], aB + g * 16 * 80 + s * 32);
                ldsm4(bl[g], aB + 10240 + g * 16 * 80 + s * 32);
            }
            #pragma unroll
            for (int f = 0; f < 4; f++)
                #pragma unroll
                for (int n = 0; n < 4; n++) {
                    mma16816(acc[f][n], ah[f], bh[n >> 1][(n & 1) * 2], bh[n >> 1][(n & 1) * 2 + 1]);
                    mma16816(acc[f][n], ah[f], bl[n >> 1][(n & 1) * 2], bl[n >> 1][(n & 1) * 2 + 1]);
                    mma16816(acc[f][n], al[f], bh[n >> 1][(n & 1) * 2], bh[n >> 1][(n & 1) * 2 + 1]);
                }
        }
        __syncthreads();
        if (c + 2 < 16)
            issue_chunk(sb + (c & 1) * TBUF, Xh, Xl, Wh, Wl, (c + 2) * 32, tid);
    }

    // epilogue
    #pragma unroll
    for (int f = 0; f < 4; f++) {
        int row = mb + wm + f * 16 + (lane >> 2);
        float* gp0 = g_G + ((size_t)d * BT + row) * H3 + nb;
        float* gp1 = gp0 + 8 * H3;
        #pragma unroll
        for (int n = 0; n < 4; n++) {
            int col = wn + n * 8 + (lane & 3) * 2;
            float b0 = __ldg(bias + col), b1 = __ldg(bias + col + 1);
            *(float2*)(gp0 + col) = make_float2(acc[f][n][0] + b0, acc[f][n][1] + b1);
            *(float2*)(gp1 + col) = make_float2(acc[f][n][2] + b0, acc[f][n][3] + b1);
        }
    }
}

// ---------------------------------------------------------------- grid barrier (monotonic)
__device__ __forceinline__ void grid_barrier(unsigned target)
{
    __syncthreads();
    if (threadIdx.x == 0) {
        __threadfence();
        unsigned a = atomicAdd(&g_cnt, 1u) + 1u;
        if (a == target * NCTA) {
            atomicAdd(&g_gen, 1u);
        } else {
            while (*(volatile unsigned*)&g_gen < target) { }
        }
        __threadfence();
    }
    __syncthreads();
}

// ---------------------------------------------------------------- K2: persistent bi-GRU recurrence
extern __shared__ float smem_gru[];
__global__ void __launch_bounds__(256) k_gru(
    const float* __restrict__ Whh_f, const float* __restrict__ bhh_f,
    const float* __restrict__ Whh_b, const float* __restrict__ bhh_b,
    const int*   __restrict__ lengths)
{
    float* Ws  = smem_gru;            // [512][96]
    float* hsm = smem_gru + 512 * 96; // [32][72]
    int tid = threadIdx.x;
    int cid = blockIdx.x;
    int d  = cid >> 6;
    int r  = cid & 63;
    int kg = r & 15;
    int bg = r >> 4;
    const float* Whh = d ? Whh_b : Whh_f;
    const float* bhh = d ? bhh_b : bhh_f;
    int tx = tid & 31, ty = tid >> 5;
    int u  = kg * 32 + tx;
    int b0 = bg * 32 + ty * 4;

    for (int idx = tid; idx < 96 * 128; idx += 256) {
        int row = idx >> 7;
        int g = row >> 5, jl = row & 31;
        int k4 = (idx & 127) << 2;
        float4 w = *(const float4*)(Whh + (long)(g * 512 + kg * 32 + jl) * 512 + k4);
        Ws[(k4+0)*96 + row] = w.x;
        Ws[(k4+1)*96 + row] = w.y;
        Ws[(k4+2)*96 + row] = w.z;
        Ws[(k4+3)*96 + row] = w.w;
    }
    float bh0 = bhh[u], bh1 = bhh[512 + u], bh2 = bhh[1024 + u];
    int len[4];
    #pragma unroll
    for (int i = 0; i < 4; i++) len[i] = lengths[b0 + i];

    for (int i = tid; i < 1024; i += 256) {
        int bb = bg * 32 + (i >> 5);
        int uu = kg * 32 + (i & 31);
        g_h[((0 * 2 + d) * 128 + bb) * 512 + uu] = 0.f;
    }
    grid_barrier(1);

    for (int t = 0; t < 512; ++t) {
        int p = t & 1;
        const float* hbase = g_h + (p * 2 + d) * 128 * 512;
        float ir[4], iz[4], inn[4];
        #pragma unroll
        for (int i = 0; i < 4; i++) {
            const float* gp = g_G + (long)d * BT * H3 + ((long)(b0 + i) * 512 + t) * H3;
            ir[i]  = __ldg(gp + u);
            iz[i]  = __ldg(gp + 512 + u);
            inn[i] = __ldg(gp + 1024 + u);
        }
        float a0[4] = {0,0,0,0}, a1[4] = {0,0,0,0}, a2[4] = {0,0,0,0};

        for (int kc = 0; kc < 512; kc += 64) {
            __syncthreads();
            {
                int bl = tid >> 3;
                int kk = (tid & 7) << 3;
                const float* hp = hbase + (bg * 32 + bl) * 512 + kc + kk;
                float4 h0 = __ldcg((const float4*)hp);
                float4 h1 = __ldcg((const float4*)(hp + 4));
                float* dst = hsm + bl * 72 + kk;
                *(float4*)dst       = h0;
                *(float4*)(dst + 4) = h1;
            }
            __syncthreads();
            #pragma unroll 16
            for (int k = 0; k < 64; k++) {
                const float* wp = Ws + (kc + k) * 96;
                float w0 = wp[tx], w1 = wp[32 + tx], w2 = wp[64 + tx];
                #pragma unroll
                for (int i = 0; i < 4; i++) {
                    float hv = hsm[(ty * 4 + i) * 72 + k];
                    a0[i] = fmaf(hv, w0, a0[i]);
                    a1[i] = fmaf(hv, w1, a1[i]);
                    a2[i] = fmaf(hv, w2, a2[i]);
                }
            }
        }
        float* hw = g_h + ((p ^ 1) * 2 + d) * 128 * 512;
        #pragma unroll
        for (int i = 0; i < 4; i++) {
            int bb = b0 + i;
            float hprev = __ldcg(hbase + bb * 512 + u);
            float rr = 1.f / (1.f + expf(-(ir[i]  + a0[i] + bh0)));
            float zz = 1.f / (1.f + expf(-(iz[i]  + a1[i] + bh1)));
            float nn = tanhf(inn[i] + rr * (a2[i] + bh2));
            float hn = (1.f - zz) * nn + zz * hprev;
            bool m = (t < len[i]);
            hw[bb * 512 + u] = m ? hn : hprev;
            float* ob = g_out + (long)bb * 512 * 1024;
            if (d == 0) {
                ob[(long)t * 1024 + u] = m ? hn : 0.f;
            } else {
                int row = m ? (len[i] - 1 - t) : t;
                ob[(long)row * 1024 + 512 + u] = m ? hn : 0.f;
            }
        }
        grid_barrier((unsigned)(t + 2));
    }
    __syncthreads();
    if (tid == 0) {
        unsigned old = atomicAdd(&g_done, 1u);
        if (old == NCTA - 1) { g_cnt = 0; g_gen = 0; g_done = 0; __threadfence(); }
    }
}

// ---------------------------------------------------------------- K3: scores += tanh(out@Wp^T+bp) . ctx
__global__ void __launch_bounds__(256) k_gemm_proj(
    const float* __restrict__ Wp, const float* __restrict__ bp,
    const float* __restrict__ ctx)
{
    __shared__ float As[8][128], Bs[8][128];
    int tid = threadIdx.x;
    int mb = blockIdx.x * 128, nb = blockIdx.y * 128;
    int lm = tid >> 1, lk = (tid & 1) * 4;
    const float* Arow = g_out + (long)(mb + lm) * 1024;
    const float* Brow = Wp    + (long)(nb + lm) * 1024;
    int tx = tid & 15, ty = tid >> 4;
    int m0 = ty * 8, n0 = tx * 8;
    float acc[8][8];
    #pragma unroll
    for (int i = 0; i < 8; i++)
        #pragma unroll
        for (int j = 0; j < 8; j++) acc[i][j] = 0.f;

    for (int kt = 0; kt < 1024; kt += 8) {
        float4 a = *(const float4*)(Arow + kt + lk);
        float4 w = *(const float4*)(Brow + kt + lk);
        As[lk+0][lm]=a.x; As[lk+1][lm]=a.y; As[lk+2][lm]=a.z; As[lk+3][lm]=a.w;
        Bs[lk+0][lm]=w.x; Bs[lk+1][lm]=w.y; Bs[lk+2][lm]=w.z; Bs[lk+3][lm]=w.w;
        __syncthreads();
        #pragma unroll
        for (int k = 0; k < 8; k++) {
            float av[8], wv[8];
            *(float4*)av     = *(float4*)&As[k][m0];
            *(float4*)(av+4) = *(float4*)&As[k][m0+4];
            *(float4*)wv     = *(float4*)&Bs[k][n0];
            *(float4*)(wv+4) = *(float4*)&Bs[k][n0+4];
            #pragma unroll
            for (int i = 0; i < 8; i++)
                #pragma unroll
                for (int j = 0; j < 8; j++)
                    acc[i][j] = fmaf(av[i], wv[j], acc[i][j]);
        }
        __syncthreads();
    }
    #pragma unroll
    for (int i = 0; i < 8; i++) {
        float part = 0.f;
        #pragma unroll
        for (int j = 0; j < 8; j++) {
            float v = tanhf(acc[i][j] + bp[nb + n0 + j]);
            part = fmaf(v, ctx[nb + n0 + j], part);
        }
        #pragma unroll
        for (int o = 8; o > 0; o >>= 1)
            part += __shfl_xor_sync(0xffffffffu, part, o);
        if (tx == 0) atomicAdd(&g_scores[mb + m0 + i], part);
    }
}

// ---------------------------------------------------------------- K4: softmax + pooling + SELU + logits
__global__ void __launch_bounds__(512) k_final(
    const int* __restrict__ lengths,
    const float* __restrict__ Wl, const float* __restrict__ bl,
    float* __restrict__ out, int out_size)
{
    __shared__ float sh[512];
    __shared__ float attn[512];
    __shared__ float lg[2];
    int b = blockIdx.x, tid = threadIdx.x;
    int len = lengths[b];
    float s = (tid < len) ? g_scores[b * 512 + tid] : -1e30f;
    sh[tid] = s; __syncthreads();
    for (int o = 256; o > 0; o >>= 1) { if (tid < o) sh[tid] = fmaxf(sh[tid], sh[tid + o]); __syncthreads(); }
    float mx = sh[0]; __syncthreads();
    float e = (tid < len) ? expf(s - mx) : 0.f;
    sh[tid] = e; __syncthreads();
    for (int o = 256; o > 0; o >>= 1) { if (tid < o) sh[tid] += sh[tid + o]; __syncthreads(); }
    float a = e / sh[0];
    attn[tid] = a;
    int attn_ofs = (out_size >= 65792) ? 256 : 0;
    if (out_size != 256) out[attn_ofs + b * 512 + tid] = a;
    if (tid == 0) { lg[0] = 0.f; lg[1] = 0.f; }
    __syncthreads();

    const float* ob = g_out + (long)b * 512 * 1024;
    float s0 = 0.f, s1 = 0.f;
    for (int t = 0; t < 512; t++) {
        float at = attn[t];
        s0 = fmaf(at, ob[(long)t * 1024 + tid],       s0);
        s1 = fmaf(at, ob[(long)t * 1024 + 512 + tid], s1);
    }
    const float SC = 1.0507009873554805f, AL = 1.6732632423543772f;
    s0 = (s0 > 0.f) ? SC * s0 : SC * AL * (expf(s0) - 1.f);
    s1 = (s1 > 0.f) ? SC * s1 : SC * AL * (expf(s1) - 1.f);
    float p0 = s0 * Wl[tid]        + s1 * Wl[512 + tid];
    float p1 = s0 * Wl[1024 + tid] + s1 * Wl[1536 + tid];
    #pragma unroll
    for (int o = 16; o > 0; o >>= 1) {
        p0 += __shfl_xor_sync(0xffffffffu, p0, o);
        p1 += __shfl_xor_sync(0xffffffffu, p1, o);
    }
    if ((tid & 31) == 0) { atomicAdd(&lg[0], p0); atomicAdd(&lg[1], p1); }
    __syncthreads();
    if (tid < 2 && out_size != 65536) out[b * 2 + tid] = lg[tid] + bl[tid];
}

// ---------------------------------------------------------------- launch
extern "C" void kernel_launch(void* const* d_in, const int* in_sizes, int n_in,
                              void* d_out, int out_size)
{
    const int*   tokens  = (const int*)d_in[0];
    const int*   lengths = (const int*)d_in[1];
    const float* emb     = (const float*)d_in[2];
    const float* Wih_f   = (const float*)d_in[3];
    const float* Whh_f   = (const float*)d_in[4];
    const float* bih_f   = (const float*)d_in[5];
    const float* bhh_f   = (const float*)d_in[6];
    const float* Wih_b   = (const float*)d_in[7];
    const float* Whh_b   = (const float*)d_in[8];
    const float* bih_b   = (const float*)d_in[9];
    const float* bhh_b   = (const float*)d_in[10];
    const float* Wp      = (const float*)d_in[11];
    const float* bp      = (const float*)d_in[12];
    const float* ctx     = (const float*)d_in[13];
    const float* Wl      = (const float*)d_in[14];
    const float* bl      = (const float*)d_in[15];
    float* out = (float*)d_out;

    k_init<<<BT / 256, 256>>>(tokens, lengths);
    k_convW<<<1536, 256>>>(Wih_f, Wih_b);
    k_convX<<<65536, 256>>>(emb);

    cudaFuncSetAttribute(k_gemm_ih_tc, cudaFuncAttributeMaxDynamicSharedMemorySize, SMEM_TC);
    dim3 g1(12, 512, 2);
    k_gemm_ih_tc<<<g1, 256, SMEM_TC>>>(bih_f, bih_b);

    int smem_bytes = (512 * 96 + 32 * 72) * 4;
    cudaFuncSetAttribute(k_gru, cudaFuncAttributeMaxDynamicSharedMemorySize, smem_bytes);
    k_gru<<<NCTA, 256, smem_bytes>>>(Whh_f, bhh_f, Whh_b, bhh_b, lengths);

    dim3 g3(512, 4);
    k_gemm_proj<<<g3, 256>>>(Wp, bp, ctx);

    k_final<<<Bsz, 512>>>(lengths, Wl, bl, out, out_size);
}

// round 6
// speedup vs baseline: 2.6031x; 1.8545x over previous
#include <cuda_runtime.h>
#include <cuda_bf16.h>
#include <math.h>
#include <stdint.h>

#define Bsz 128
#define Tt  512
#define H3  1536
#define BT  65536
#define NCTA 128

__device__ float g_G[201326592];    // [dir][b*T+t][1536]
__device__ float g_out[67108864];   // [b][t][1024] fp32
__device__ __nv_bfloat16 g_outh[67108864];
__device__ __nv_bfloat16 g_outl[67108864];
__device__ float g_scores[65536];
__device__ int   g_tok2[131072];
__device__ unsigned g_cnt4[4], g_gen4[4], g_done;

// bf16 split operands
__device__ __nv_bfloat16 g_Xh[67108864];  // [2*BT][512]
__device__ __nv_bfloat16 g_Xl[67108864];
__device__ __nv_bfloat16 g_Wh[1572864];   // [2][1536][512]
__device__ __nv_bfloat16 g_Wl[1572864];
__device__ __nv_bfloat16 g_Wph[524288];   // [512][1024]
__device__ __nv_bfloat16 g_Wpl[524288];
__device__ __nv_bfloat16 g_hbh[262144];   // [ph][d][128][512]
__device__ __nv_bfloat16 g_hbl[262144];

// ---------------------------------------------------------------- helpers
__device__ __forceinline__ uint32_t smem_u32(const void* p)
{
    uint32_t a;
    asm("{ .reg .u64 t; cvta.to.shared.u64 t, %1; cvt.u32.u64 %0, t; }" : "=r"(a) : "l"(p));
    return a;
}
__device__ __forceinline__ void cp16(uint32_t dst, const void* src)
{
    asm volatile("cp.async.cg.shared.global [%0], [%1], 16;" :: "r"(dst), "l"(src) : "memory");
}
__device__ __forceinline__ void cp_commit()
{
    asm volatile("cp.async.commit_group;" ::: "memory");
}
__device__ __forceinline__ void ldsm4(uint32_t* r, uint32_t addr)
{
    asm volatile("ldmatrix.sync.aligned.m8n8.x4.shared.b16 {%0,%1,%2,%3}, [%4];"
                 : "=r"(r[0]), "=r"(r[1]), "=r"(r[2]), "=r"(r[3]) : "r"(addr));
}
__device__ __forceinline__ void ldsm2(uint32_t* r, uint32_t addr)
{
    asm volatile("ldmatrix.sync.aligned.m8n8.x2.shared.b16 {%0,%1}, [%2];"
                 : "=r"(r[0]), "=r"(r[1]) : "r"(addr));
}
__device__ __forceinline__ void mma16816(float* c, const uint32_t* a, uint32_t b0, uint32_t b1)
{
    asm volatile("mma.sync.aligned.m16n8k16.row.col.f32.bf16.bf16.f32 "
                 "{%0,%1,%2,%3}, {%4,%5,%6,%7}, {%8,%9}, {%0,%1,%2,%3};"
                 : "+f"(c[0]), "+f"(c[1]), "+f"(c[2]), "+f"(c[3])
                 : "r"(a[0]), "r"(a[1]), "r"(a[2]), "r"(a[3]), "r"(b0), "r"(b1));
}
__device__ __forceinline__ void split_bf16(float v, __nv_bfloat16& h, __nv_bfloat16& l)
{
    h = __float2bfloat16(v);
    l = __float2bfloat16(v - __bfloat162float(h));
}

// ---------------------------------------------------------------- K0
__global__ void k_init(const int* __restrict__ tokens, const int* __restrict__ lengths)
{
    int i = blockIdx.x * blockDim.x + threadIdx.x;
    if (i >= BT) return;
    int b = i >> 9, t = i & 511;
    g_tok2[i] = tokens[i];
    int rt = lengths[b] - 1 - t;
    if (rt < 0) rt = 0;
    g_tok2[BT + i] = tokens[(b << 9) + rt];
    g_scores[i] = 0.f;
    ((uint2*)g_hbh)[i] = make_uint2(0u, 0u);
    ((uint2*)g_hbl)[i] = make_uint2(0u, 0u);
}

// ---------------------------------------------------------------- conv kernels
__global__ void k_convX(const float* __restrict__ emb)
{
    size_t idx = (size_t)blockIdx.x * 256 + threadIdx.x;
    size_t e = idx * 4;
    size_t row = e >> 9;
    int k = (int)(e & 511);
    int tok = g_tok2[row];
    float4 v = *(const float4*)(emb + (size_t)tok * 512 + k);
    float vv[4] = {v.x, v.y, v.z, v.w};
    __nv_bfloat16 h[4], l[4];
    #pragma unroll
    for (int j = 0; j < 4; j++) split_bf16(vv[j], h[j], l[j]);
    __nv_bfloat162* ph = (__nv_bfloat162*)(g_Xh + row * 512 + k);
    __nv_bfloat162* pl = (__nv_bfloat162*)(g_Xl + row * 512 + k);
    ph[0] = __nv_bfloat162{h[0], h[1]}; ph[1] = __nv_bfloat162{h[2], h[3]};
    pl[0] = __nv_bfloat162{l[0], l[1]}; pl[1] = __nv_bfloat162{l[2], l[3]};
}

__global__ void k_convW(const float* __restrict__ Wf, const float* __restrict__ Wb)
{
    size_t idx = (size_t)blockIdx.x * 256 + threadIdx.x;
    size_t e = idx * 4;
    size_t row = e >> 9;
    int k = (int)(e & 511);
    int d = (int)(row >= 1536);
    size_t n = row - (size_t)d * 1536;
    const float* W = d ? Wb : Wf;
    float4 v = *(const float4*)(W + n * 512 + k);
    float vv[4] = {v.x, v.y, v.z, v.w};
    __nv_bfloat16 h[4], l[4];
    #pragma unroll
    for (int j = 0; j < 4; j++) split_bf16(vv[j], h[j], l[j]);
    __nv_bfloat162* ph = (__nv_bfloat162*)(g_Wh + row * 512 + k);
    __nv_bfloat162* pl = (__nv_bfloat162*)(g_Wl + row * 512 + k);
    ph[0] = __nv_bfloat162{h[0], h[1]}; ph[1] = __nv_bfloat162{h[2], h[3]};
    pl[0] = __nv_bfloat162{l[0], l[1]}; pl[1] = __nv_bfloat162{l[2], l[3]};
}

__global__ void k_convP(const float* __restrict__ Wp)
{
    size_t idx = (size_t)blockIdx.x * 256 + threadIdx.x;
    size_t e = idx * 4;   // 512*1024 elems / 4
    float4 v = *(const float4*)(Wp + e);
    float vv[4] = {v.x, v.y, v.z, v.w};
    __nv_bfloat16 h[4], l[4];
    #pragma unroll
    for (int j = 0; j < 4; j++) split_bf16(vv[j], h[j], l[j]);
    __nv_bfloat162* ph = (__nv_bfloat162*)(g_Wph + e);
    __nv_bfloat162* pl = (__nv_bfloat162*)(g_Wpl + e);
    ph[0] = __nv_bfloat162{h[0], h[1]}; ph[1] = __nv_bfloat162{h[2], h[3]};
    pl[0] = __nv_bfloat162{l[0], l[1]}; pl[1] = __nv_bfloat162{l[2], l[3]};
}

// ---------------------------------------------------------------- shared GEMM staging
// Per buffer (40960 B): Ah@0, Al@10240, Bh@20480, Bl@30720; rows stride 80 B (32 k bf16 + pad)
#define TBUF 40960
#define SMEM_TC (2 * TBUF)
extern __shared__ char sm_tc[];

__device__ __forceinline__ void issue_chunk(
    uint32_t sbase, const __nv_bfloat16* Ah, const __nv_bfloat16* Al,
    const __nv_bfloat16* Bh, const __nv_bfloat16* Bl, int k0, int tid, int ldk)
{
    const __nv_bfloat16* srcs[4] = {Ah, Al, Bh, Bl};
    #pragma unroll
    for (int j = 0; j < 8; j++) {
        int L = tid + j * 256;
        int mat = L >> 9, rem = L & 511, row = rem >> 2, q = rem & 3;
        const char* gp = (const char*)(srcs[mat] + (size_t)row * ldk + k0) + q * 16;
        cp16(sbase + mat * 10240 + row * 80 + q * 16, gp);
    }
    cp_commit();
}

// ---------------------------------------------------------------- K1: input-gate GEMM (tensor)
__global__ void __launch_bounds__(256) k_gemm_ih_tc(
    const float* __restrict__ bf, const float* __restrict__ bb)
{
    uint32_t sb = smem_u32(sm_tc);
    int tid = threadIdx.x, wid = tid >> 5, lane = tid & 31;
    int d = blockIdx.z, mb = blockIdx.y * 128, nb = blockIdx.x * 128;
    const float* bias = (d ? bb : bf) + nb;

    const __nv_bfloat16* Xh = g_Xh + (size_t)(d * BT + mb) * 512;
    const __nv_bfloat16* Xl = g_Xl + (size_t)(d * BT + mb) * 512;
    const __nv_bfloat16* Wh = g_Wh + (size_t)(d * 1536 + nb) * 512;
    const __nv_bfloat16* Wl = g_Wl + (size_t)(d * 1536 + nb) * 512;

    int wm = (wid & 1) * 64;
    int wn = (wid >> 1) * 32;

    float acc[4][4][4];
    #pragma unroll
    for (int f = 0; f < 4; f++)
        #pragma unroll
        for (int n = 0; n < 4; n++)
            #pragma unroll
            for (int r = 0; r < 4; r++) acc[f][n][r] = 0.f;

    issue_chunk(sb,        Xh, Xl, Wh, Wl, 0,  tid, 512);
    issue_chunk(sb + TBUF, Xh, Xl, Wh, Wl, 32, tid, 512);

    int arow = (lane & 15);
    int ahk  = ((lane >> 4) & 1) * 16;
    int brow = (lane & 7) + ((lane >> 4) & 1) * 8;
    int bhk  = ((lane >> 3) & 1) * 16;

    for (int c = 0; c < 16; c++) {
        if (c == 15) asm volatile("cp.async.wait_group 0;" ::: "memory");
        else         asm volatile("cp.async.wait_group 1;" ::: "memory");
        __syncthreads();
        uint32_t base = sb + (c & 1) * TBUF;
        uint32_t aA = base +         (wm + arow) * 80 + ahk;
        uint32_t aB = base + 20480 + (wn + brow) * 80 + bhk;

        #pragma unroll
        for (int s = 0; s < 2; s++) {
            uint32_t ah[4][4], al[4][4], bh[2][4], bl[2][4];
            #pragma unroll
            for (int f = 0; f < 4; f++) {
                ldsm4(ah[f], aA + f * 16 * 80 + s * 32);
                ldsm4(al[f], aA + 10240 + f * 16 * 80 + s * 32);
            }
            #pragma unroll
            for (int g = 0; g < 2; g++) {
                ldsm4(bh[g], aB + g * 16 * 80 + s * 32);
                ldsm4(bl[g], aB + 10240 + g * 16 * 80 + s * 32);
            }
            #pragma unroll
            for (int f = 0; f < 4; f++)
                #pragma unroll
                for (int n = 0; n < 4; n++) {
                    mma16816(acc[f][n], ah[f], bh[n >> 1][(n & 1) * 2], bh[n >> 1][(n & 1) * 2 + 1]);
                    mma16816(acc[f][n], ah[f], bl[n >> 1][(n & 1) * 2], bl[n >> 1][(n & 1) * 2 + 1]);
                    mma16816(acc[f][n], al[f], bh[n >> 1][(n & 1) * 2], bh[n >> 1][(n & 1) * 2 + 1]);
                }
        }
        __syncthreads();
        if (c + 2 < 16)
            issue_chunk(sb + (c & 1) * TBUF, Xh, Xl, Wh, Wl, (c + 2) * 32, tid, 512);
    }

    #pragma unroll
    for (int f = 0; f < 4; f++) {
        int row = mb + wm + f * 16 + (lane >> 2);
        float* gp0 = g_G + ((size_t)d * BT + row) * H3 + nb;
        float* gp1 = gp0 + 8 * H3;
        #pragma unroll
        for (int n = 0; n < 4; n++) {
            int col = wn + n * 8 + (lane & 3) * 2;
            float b0 = __ldg(bias + col), b1 = __ldg(bias + col + 1);
            *(float2*)(gp0 + col) = make_float2(acc[f][n][0] + b0, acc[f][n][1] + b1);
            *(float2*)(gp1 + col) = make_float2(acc[f][n][2] + b0, acc[f][n][3] + b1);
        }
    }
}

// ---------------------------------------------------------------- group barrier
__device__ __forceinline__ void group_barrier(int gid, unsigned target)
{
    __syncthreads();
    if (threadIdx.x == 0) {
        __threadfence();
        unsigned a = atomicAdd(&g_cnt4[gid], 1u) + 1u;
        if (a == target * 32u) {
            atomicAdd(&g_gen4[gid], 1u);
        } else {
            while (*(volatile unsigned*)&g_gen4[gid] < target) { }
        }
        __threadfence();
    }
    __syncthreads();
}

// ---------------------------------------------------------------- K2: tensor-core bi-GRU recurrence
// CTA: d = cid>>6, bg = (cid>>5)&1 (64-batch half), ng = cid&31 (16 hidden units -> 48 gate rows)
// smem: Wh 49920 | Wl 49920 | H 2 bufs x (hi 17408 + lo 17408) | gate 64x52 fp32
#define K2_WH   0
#define K2_WL   49920
#define K2_H    99840
#define K2_GATE 169472
#define K2_SMEM 182784
extern __shared__ char sm2[];
__global__ void __launch_bounds__(256) k_gru_tc(
    const float* __restrict__ Whh_f, const float* __restrict__ bhh_f,
    const float* __restrict__ Whh_b, const float* __restrict__ bhh_b,
    const int*   __restrict__ lengths)
{
    uint32_t sb = smem_u32(sm2);
    int tid = threadIdx.x, wid = tid >> 5, lane = tid & 31;
    int cid = blockIdx.x;
    int d = cid >> 6, bg = (cid >> 5) & 1, ng = cid & 31;
    int gid = d * 2 + bg;
    const float* Whh = d ? Whh_b : Whh_f;
    const float* bhh = d ? bhh_b : bhh_f;

    // Whh slice -> smem bf16 hi/lo (rows: 0-15 r, 16-31 z, 32-47 n for units ng*16..+15)
    for (int i = tid; i < 48 * 128; i += 256) {
        int row = i >> 7, k4 = (i & 127) << 2;
        int g = row >> 4, ul = row & 15;
        float4 w = *(const float4*)(Whh + (size_t)(g * 512 + ng * 16 + ul) * 512 + k4);
        float vv[4] = {w.x, w.y, w.z, w.w};
        __nv_bfloat16 h[4], l[4];
        #pragma unroll
        for (int j = 0; j < 4; j++) split_bf16(vv[j], h[j], l[j]);
        char* ph = sm2 + K2_WH + row * 1040 + k4 * 2;
        char* pl = sm2 + K2_WL + row * 1040 + k4 * 2;
        *(__nv_bfloat162*)ph       = __nv_bfloat162{h[0], h[1]};
        *(__nv_bfloat162*)(ph + 4) = __nv_bfloat162{h[2], h[3]};
        *(__nv_bfloat162*)pl       = __nv_bfloat162{l[0], l[1]};
        *(__nv_bfloat162*)(pl + 4) = __nv_bfloat162{l[2], l[3]};
    }

    int b_loc  = tid >> 2;              // 0..63
    int u0     = (tid & 3) * 4;         // 0,4,8,12
    int b_glob = bg * 64 + b_loc;
    int len_b  = lengths[b_glob];
    float bh_r[4], bh_z[4], bh_n[4];
    #pragma unroll
    for (int j = 0; j < 4; j++) {
        int u = ng * 16 + u0 + j;
        bh_r[j] = bhh[u]; bh_z[j] = bhh[512 + u]; bh_n[j] = bhh[1024 + u];
    }
    float hprev[4] = {0.f, 0.f, 0.f, 0.f};

    int m0  = (wid & 3) * 16;
    int n0w = (wid >> 2) * 24;
    uint32_t aoffA  = (uint32_t)((m0 + (lane & 15)) * 272 + ((lane >> 4) & 1) * 16);
    uint32_t aoffB4 = (uint32_t)((n0w + (lane & 7) + ((lane >> 4) & 1) * 8) * 1040 + ((lane >> 3) & 1) * 16);
    uint32_t aoffB2 = (uint32_t)((n0w + 16 + (lane & 7)) * 1040 + ((lane >> 3) & 1) * 16);

    float* gsm = (float*)(sm2 + K2_GATE);
    __syncthreads();

    for (int t = 0; t < 512; t++) {
        int ph = t & 1;
        // prefetch input gates
        const float* gp = g_G + (size_t)d * BT * H3 + ((size_t)b_glob * 512 + t) * H3 + ng * 16 + u0;
        float4 gir = __ldg((const float4*)gp);
        float4 giz = __ldg((const float4*)(gp + 512));
        float4 gin = __ldg((const float4*)(gp + 1024));

        size_t hsrc = ((size_t)(ph * 2 + d) * 128 + bg * 64) * 512;
        // stage chunk 0
        {
            uint32_t dsth = sb + K2_H;
            #pragma unroll
            for (int j = 0; j < 4; j++) {
                int L = tid + j * 256;
                int row = L >> 4, q = L & 15;
                cp16(dsth + row * 272 + q * 16,         (const char*)(g_hbh + hsrc + (size_t)row * 512) + q * 16);
                cp16(dsth + 17408 + row * 272 + q * 16, (const char*)(g_hbl + hsrc + (size_t)row * 512) + q * 16);
            }
            cp_commit();
        }

        float acc[3][4];
        #pragma unroll
        for (int n = 0; n < 3; n++)
            #pragma unroll
            for (int r = 0; r < 4; r++) acc[n][r] = 0.f;

        for (int c = 0; c < 4; c++) {
            if (c < 3) {
                int kc = (c + 1) * 128;
                uint32_t dsth = sb + K2_H + ((c + 1) & 1) * 34816;
                #pragma unroll
                for (int j = 0; j < 4; j++) {
                    int L = tid + j * 256;
                    int row = L >> 4, q = L & 15;
                    cp16(dsth + row * 272 + q * 16,         (const char*)(g_hbh + hsrc + (size_t)row * 512 + kc) + q * 16);
                    cp16(dsth + 17408 + row * 272 + q * 16, (const char*)(g_hbl + hsrc + (size_t)row * 512 + kc) + q * 16);
                }
                cp_commit();
                asm volatile("cp.async.wait_group 1;" ::: "memory");
            } else {
                asm volatile("cp.async.wait_group 0;" ::: "memory");
            }
            __syncthreads();
            uint32_t hb_hi = sb + K2_H + (c & 1) * 34816;
            uint32_t hb_lo = hb_hi + 17408;
            #pragma unroll
            for (int kt = 0; kt < 8; kt++) {
                uint32_t koffH = kt * 32;
                uint32_t koffW = (uint32_t)(c * 128 + kt * 16) * 2;
                uint32_t ah[4], al[4], bh4[4], b2h[2], bl4[4], b2l[2];
                ldsm4(ah, hb_hi + aoffA + koffH);
                ldsm4(al, hb_lo + aoffA + koffH);
                ldsm4(bh4, sb + K2_WH + aoffB4 + koffW);
                ldsm2(b2h, sb + K2_WH + aoffB2 + koffW);
                ldsm4(bl4, sb + K2_WL + aoffB4 + koffW);
                ldsm2(b2l, sb + K2_WL + aoffB2 + koffW);
                mma16816(acc[0], ah, bh4[0], bh4[1]);
                mma16816(acc[1], ah, bh4[2], bh4[3]);
                mma16816(acc[2], ah, b2h[0], b2h[1]);
                mma16816(acc[0], ah, bl4[0], bl4[1]);
                mma16816(acc[1], ah, bl4[2], bl4[3]);
                mma16816(acc[2], ah, b2l[0], b2l[1]);
                mma16816(acc[0], al, bh4[0], bh4[1]);
                mma16816(acc[1], al, bh4[2], bh4[3]);
                mma16816(acc[2], al, b2h[0], b2h[1]);
            }
            __syncthreads();
        }

        // write gate pre-activations to smem
        int grow = m0 + (lane >> 2);
        #pragma unroll
        for (int j = 0; j < 3; j++) {
            int col = n0w + j * 8 + (lane & 3) * 2;
            gsm[grow * 52 + col]           = acc[j][0];
            gsm[grow * 52 + col + 1]       = acc[j][1];
            gsm[(grow + 8) * 52 + col]     = acc[j][2];
            gsm[(grow + 8) * 52 + col + 1] = acc[j][3];
        }
        __syncthreads();

        // gate math + outputs
        float gi_r[4], gi_z[4], gi_n[4];
        *(float4*)gi_r = gir; *(float4*)gi_z = giz; *(float4*)gi_n = gin;
        bool m = (t < len_b);
        size_t hwb = ((size_t)((ph ^ 1) * 2 + d) * 128 + b_glob) * 512 + ng * 16;
        int orow = (d == 0) ? t : (m ? (len_b - 1 - t) : t);
        size_t ob = ((size_t)b_glob * 512 + orow) * 1024 + d * 512 + ng * 16;
        #pragma unroll
        for (int j = 0; j < 4; j++) {
            int u = u0 + j;
            float ar = gsm[b_loc * 52 + u];
            float az = gsm[b_loc * 52 + 16 + u];
            float an = gsm[b_loc * 52 + 32 + u];
            float rr = 1.f / (1.f + expf(-(gi_r[j] + ar + bh_r[j])));
            float zz = 1.f / (1.f + expf(-(gi_z[j] + az + bh_z[j])));
            float nn = tanhf(gi_n[j] + rr * (an + bh_n[j]));
            float hn = (1.f - zz) * nn + zz * hprev[j];
            float hm = m ? hn : hprev[j];
            hprev[j] = hm;
            __nv_bfloat16 hh, hl;
            split_bf16(hm, hh, hl);
            g_hbh[hwb + u] = hh;
            g_hbl[hwb + u] = hl;
            float ov = m ? hn : 0.f;
            g_out[ob + u] = ov;
            __nv_bfloat16 oh, ol;
            split_bf16(ov, oh, ol);
            g_outh[ob + u] = oh;
            g_outl[ob + u] = ol;
        }
        group_barrier(gid, (unsigned)(t + 1));
    }

    if (tid == 0) {
        unsigned old = atomicAdd(&g_done, 1u);
        if (old == NCTA - 1) {
            #pragma unroll
            for (int g = 0; g < 4; g++) { g_cnt4[g] = 0; g_gen4[g] = 0; }
            g_done = 0;
            __threadfence();
        }
    }
}

// ---------------------------------------------------------------- K3: tensor proj + fused ctx-dot
__global__ void __launch_bounds__(256) k_gemm_proj_tc(
    const float* __restrict__ bp, const float* __restrict__ ctx)
{
    uint32_t sb = smem_u32(sm_tc);
    int tid = threadIdx.x, wid = tid >> 5, lane = tid & 31;
    int mb = blockIdx.y * 128, nb = blockIdx.x * 128;

    const __nv_bfloat16* Ah = g_outh + (size_t)mb * 1024;
    const __nv_bfloat16* Al = g_outl + (size_t)mb * 1024;
    const __nv_bfloat16* Bh = g_Wph + (size_t)nb * 1024;
    const __nv_bfloat16* Bl = g_Wpl + (size_t)nb * 1024;

    int wm = (wid & 1) * 64;
    int wn = (wid >> 1) * 32;

    float acc[4][4][4];
    #pragma unroll
    for (int f = 0; f < 4; f++)
        #pragma unroll
        for (int n = 0; n < 4; n++)
            #pragma unroll
            for (int r = 0; r < 4; r++) acc[f][n][r] = 0.f;

    issue_chunk(sb,        Ah, Al, Bh, Bl, 0,  tid, 1024);
    issue_chunk(sb + TBUF, Ah, Al, Bh, Bl, 32, tid, 1024);

    int arow = (lane & 15);
    int ahk  = ((lane >> 4) & 1) * 16;
    int brow = (lane & 7) + ((lane >> 4) & 1) * 8;
    int bhk  = ((lane >> 3) & 1) * 16;

    for (int c = 0; c < 32; c++) {
        if (c == 31) asm volatile("cp.async.wait_group 0;" ::: "memory");
        else         asm volatile("cp.async.wait_group 1;" ::: "memory");
        __syncthreads();
        uint32_t base = sb + (c & 1) * TBUF;
        uint32_t aA = base +         (wm + arow) * 80 + ahk;
        uint32_t aB = base + 20480 + (wn + brow) * 80 + bhk;

        #pragma unroll
        for (int s = 0; s < 2; s++) {
            uint32_t ah[4][4], al[4][4], bh[2][4], bl[2][4];
            #pragma unroll
            for (int f = 0; f < 4; f++) {
                ldsm4(ah[f], aA + f * 16 * 80 + s * 32);
                ldsm4(al[f], aA + 10240 + f * 16 * 80 + s * 32);
            }
            #pragma unroll
            for (int g = 0; g < 2; g++) {
                ldsm4(bh[g], aB + g * 16 * 80 + s * 32);
                ldsm4(bl[g], aB + 10240 + g * 16 * 80 + s * 32);
            }
            #pragma unroll
            for (int f = 0; f < 4; f++)
                #pragma unroll
                for (int n = 0; n < 4; n++) {
                    mma16816(acc[f][n], ah[f], bh[n >> 1][(n & 1) * 2], bh[n >> 1][(n & 1) * 2 + 1]);
                    mma16816(acc[f][n], ah[f], bl[n >> 1][(n & 1) * 2], bl[n >> 1][(n & 1) * 2 + 1]);
                    mma16816(acc[f][n], al[f], bh[n >> 1][(n & 1) * 2], bh[n >> 1][(n & 1) * 2 + 1]);
                }
        }
        __syncthreads();
        if (c + 2 < 32)
            issue_chunk(sb + (c & 1) * TBUF, Ah, Al, Bh, Bl, (c + 2) * 32, tid, 1024);
    }

    // fused epilogue: scores[row] += sum_col tanh(acc + bp[col]) * ctx[col]
    #pragma unroll
    for (int f = 0; f < 4; f++) {
        int r0 = mb + wm + f * 16 + (lane >> 2);
        float p0 = 0.f, p1 = 0.f;
        #pragma unroll
        for (int n = 0; n < 4; n++) {
            int col = nb + wn + n * 8 + (lane & 3) * 2;
            float c0 = __ldg(ctx + col), c1 = __ldg(ctx + col + 1);
            float b0 = __ldg(bp + col),  b1 = __ldg(bp + col + 1);
            p0 += tanhf(acc[f][n][0] + b0) * c0 + tanhf(acc[f][n][1] + b1) * c1;
            p1 += tanhf(acc[f][n][2] + b0) * c0 + tanhf(acc[f][n][3] + b1) * c1;
        }
        p0 += __shfl_xor_sync(0xffffffffu, p0, 1);
        p0 += __shfl_xor_sync(0xffffffffu, p0, 2);
        p1 += __shfl_xor_sync(0xffffffffu, p1, 1);
        p1 += __shfl_xor_sync(0xffffffffu, p1, 2);
        if ((lane & 3) == 0) {
            atomicAdd(&g_scores[r0], p0);
            atomicAdd(&g_scores[r0 + 8], p1);
        }
    }
}

// ---------------------------------------------------------------- K4: softmax + pooling + SELU + logits
__global__ void __launch_bounds__(512) k_final(
    const int* __restrict__ lengths,
    const float* __restrict__ Wl, const float* __restrict__ bl,
    float* __restrict__ out, int out_size)
{
    __shared__ float sh[512];
    __shared__ float attn[512];
    __shared__ float lg[2];
    int b = blockIdx.x, tid = threadIdx.x;
    int len = lengths[b];
    float s = (tid < len) ? g_scores[b * 512 + tid] : -1e30f;
    sh[tid] = s; __syncthreads();
    for (int o = 256; o > 0; o >>= 1) { if (tid < o) sh[tid] = fmaxf(sh[tid], sh[tid + o]); __syncthreads(); }
    float mx = sh[0]; __syncthreads();
    float e = (tid < len) ? expf(s - mx) : 0.f;
    sh[tid] = e; __syncthreads();
    for (int o = 256; o > 0; o >>= 1) { if (tid < o) sh[tid] += sh[tid + o]; __syncthreads(); }
    float a = e / sh[0];
    attn[tid] = a;
    int attn_ofs = (out_size >= 65792) ? 256 : 0;
    if (out_size != 256) out[attn_ofs + b * 512 + tid] = a;
    if (tid == 0) { lg[0] = 0.f; lg[1] = 0.f; }
    __syncthreads();

    const float* ob = g_out + (long)b * 512 * 1024;
    float s0 = 0.f, s1 = 0.f;
    for (int t = 0; t < 512; t++) {
        float at = attn[t];
        s0 = fmaf(at, ob[(long)t * 1024 + tid],       s0);
        s1 = fmaf(at, ob[(long)t * 1024 + 512 + tid], s1);
    }
    const float SC = 1.0507009873554805f, AL = 1.6732632423543772f;
    s0 = (s0 > 0.f) ? SC * s0 : SC * AL * (expf(s0) - 1.f);
    s1 = (s1 > 0.f) ? SC * s1 : SC * AL * (expf(s1) - 1.f);
    float p0 = s0 * Wl[tid]        + s1 * Wl[512 + tid];
    float p1 = s0 * Wl[1024 + tid] + s1 * Wl[1536 + tid];
    #pragma unroll
    for (int o = 16; o > 0; o >>= 1) {
        p0 += __shfl_xor_sync(0xffffffffu, p0, o);
        p1 += __shfl_xor_sync(0xffffffffu, p1, o);
    }
    if ((tid & 31) == 0) { atomicAdd(&lg[0], p0); atomicAdd(&lg[1], p1); }
    __syncthreads();
    if (tid < 2 && out_size != 65536) out[b * 2 + tid] = lg[tid] + bl[tid];
}

// ---------------------------------------------------------------- launch
extern "C" void kernel_launch(void* const* d_in, const int* in_sizes, int n_in,
                              void* d_out, int out_size)
{
    const int*   tokens  = (const int*)d_in[0];
    const int*   lengths = (const int*)d_in[1];
    const float* emb     = (const float*)d_in[2];
    const float* Wih_f   = (const float*)d_in[3];
    const float* Whh_f   = (const float*)d_in[4];
    const float* bih_f   = (const float*)d_in[5];
    const float* bhh_f   = (const float*)d_in[6];
    const float* Wih_b   = (const float*)d_in[7];
    const float* Whh_b   = (const float*)d_in[8];
    const float* bih_b   = (const float*)d_in[9];
    const float* bhh_b   = (const float*)d_in[10];
    const float* Wp      = (const float*)d_in[11];
    const float* bp      = (const float*)d_in[12];
    const float* ctx     = (const float*)d_in[13];
    const float* Wl      = (const float*)d_in[14];
    const float* bl      = (const float*)d_in[15];
    float* out = (float*)d_out;

    k_init<<<BT / 256, 256>>>(tokens, lengths);
    k_convW<<<1536, 256>>>(Wih_f, Wih_b);
    k_convX<<<65536, 256>>>(emb);
    k_convP<<<512, 256>>>(Wp);

    cudaFuncSetAttribute(k_gemm_ih_tc, cudaFuncAttributeMaxDynamicSharedMemorySize, SMEM_TC);
    dim3 g1(12, 512, 2);
    k_gemm_ih_tc<<<g1, 256, SMEM_TC>>>(bih_f, bih_b);

    cudaFuncSetAttribute(k_gru_tc, cudaFuncAttributeMaxDynamicSharedMemorySize, K2_SMEM);
    k_gru_tc<<<NCTA, 256, K2_SMEM>>>(Whh_f, bhh_f, Whh_b, bhh_b, lengths);

    cudaFuncSetAttribute(k_gemm_proj_tc, cudaFuncAttributeMaxDynamicSharedMemorySize, SMEM_TC);
    dim3 g3(4, 512);
    k_gemm_proj_tc<<<g3, 256, SMEM_TC>>>(bp, ctx);

    k_final<<<Bsz, 512>>>(lengths, Wl, bl, out, out_size);
}